// round 5
// baseline (speedup 1.0000x reference)
#include <cuda_runtime.h>
#include <cstdint>

#define N_NODES  4096
#define N_EDGES  16384
#define N_GRAPHS 128
#define DIM      64     // IN = H = 64 for all layers
#define EDIM     16
#define HD       4096   // DIM*DIM, edge-MLP width

// ---------------------------------------------------------------------------
// Scratch (static __device__ globals: no allocation anywhere)
// ---------------------------------------------------------------------------
__device__ float g_h[N_EDGES * HD];       // 268 MB: relu(ea@w1+b1), tf32-rounded
__device__ float g_w2r[HD * HD];          // 64 MB: tf32-rounded w2 (per layer)
__device__ float g_feat[2][N_NODES * DIM];
__device__ float g_agg[N_NODES * DIM];
__device__ float g_cnt[N_NODES];
__device__ float g_gcnt[N_GRAPHS];

__device__ __forceinline__ uint32_t f2tf32(float x) {
    uint32_t r;
    asm("cvt.rna.tf32.f32 %0, %1;" : "=r"(r) : "f"(x));
    return r;
}

// ---------------------------------------------------------------------------
// Utility: zero a float buffer
// ---------------------------------------------------------------------------
__global__ void zero_kernel(float* __restrict__ p, int n) {
    int i = blockIdx.x * blockDim.x + threadIdx.x;
    if (i < n) p[i] = 0.0f;
}

// In-degree counts (identical for all 3 layers)
__global__ void cnt_kernel(const int* __restrict__ ei) {
    int e = blockIdx.x * blockDim.x + threadIdx.x;
    if (e < N_EDGES) atomicAdd(&g_cnt[ei[N_EDGES + e]], 1.0f);
}

// w2 -> tf32-rounded copy (removes cvt from GEMM inner loop)
__global__ void round_w2_kernel(const float* __restrict__ w2) {
    int i = blockIdx.x * blockDim.x + threadIdx.x;   // float4 index
    float4 v = *reinterpret_cast<const float4*>(w2 + (size_t)i * 4);
    uint4 r;
    r.x = f2tf32(v.x); r.y = f2tf32(v.y); r.z = f2tf32(v.z); r.w = f2tf32(v.w);
    *reinterpret_cast<uint4*>(g_w2r + (size_t)i * 4) = r;
}

// ---------------------------------------------------------------------------
// h = relu(edge_attr @ w1 + b1), stored tf32-rounded.
// grid: (E/32, HD/128), block 256. Block tile: 32 edges x 128 cols.
// ---------------------------------------------------------------------------
__global__ void edge_mlp_kernel(const float* __restrict__ ea,
                                const float* __restrict__ w1,
                                const float* __restrict__ b1) {
    __shared__ float sa[32][20];    // row stride 80B: 16B-aligned float4 stores
    __shared__ float sw[16][128];
    const int e0 = blockIdx.x * 32;
    const int c0 = blockIdx.y * 128;
    const int t  = threadIdx.x;

    if (t < 128) {                         // 32 edges x 16 attrs
        int e = t >> 2, d4 = (t & 3) << 2;
        float4 v = *reinterpret_cast<const float4*>(ea + (e0 + e) * EDIM + d4);
        *reinterpret_cast<float4*>(&sa[e][d4]) = v;
    }
#pragma unroll
    for (int i = 0; i < 2; i++) {          // w1 slab 16 x 128
        int id = t + i * 256;
        int d = id >> 5, c4 = (id & 31) << 2;
        float4 v = *reinterpret_cast<const float4*>(w1 + d * HD + c0 + c4);
        *reinterpret_cast<float4*>(&sw[d][c4]) = v;
    }
    __syncthreads();

    const int lc = t & 127;                // column within tile
    const int eh = t >> 7;                 // 0/1 edge phase (constant per warp)
    float wreg[16];
#pragma unroll
    for (int d = 0; d < 16; d++) wreg[d] = sw[d][lc];
    const float bias = __ldg(b1 + c0 + lc);

#pragma unroll
    for (int j = 0; j < 16; j++) {
        int e = eh + j * 2;
        float acc = bias;
#pragma unroll
        for (int d = 0; d < 16; d++) acc += sa[e][d] * wreg[d];
        acc = fmaxf(acc, 0.0f);
        g_h[(size_t)(e0 + e) * HD + c0 + lc] = __uint_as_float(f2tf32(acc));
    }
}

// ---------------------------------------------------------------------------
// Fused: theta = g_h @ w2r + b2 and message scatter.
// [M=E=16384, N=HD=4096, K=HD=4096], TF32 mma.sync.
// BM=128 BN=256 BK=32, 2-stage cp.async pipeline, 512 threads (16 warps),
// warp grid 4x4, warp tile 32x64 (2 m-tiles x 8 n-tiles of m16n8k8).
// Each warp's 256-col slab covers exactly ONE input channel i=(n0>>6)+wn, so
// the epilogue computes x[src,i]*theta and atomicAdds into g_agg[dst] — theta
// is never materialized. b2 is folded in via acc init.
// Smem strides: A=36 (banks 4g+q), B=264 (banks 8q+g) -> conflict-free.
// ---------------------------------------------------------------------------
#define BM 128
#define BN 256
#define BK 32
#define ASTRIDE 36
#define BSTRIDE 264
#define A_STAGE (BM * ASTRIDE)            // 4608 floats
#define B_STAGE (BK * BSTRIDE)            // 8448 floats
#define STAGE   (A_STAGE + B_STAGE)       // 13056 floats
#define SMEM_BYTES (2 * STAGE * 4)        // 104448 B

__global__ __launch_bounds__(512, 1)
void gemm_scatter_kernel(const float* __restrict__ b2,
                         const float* __restrict__ xin,
                         const int* __restrict__ ei) {
    extern __shared__ float smem[];
    const int t  = threadIdx.x;
    const int m0 = blockIdx.y * BM;
    const int n0 = blockIdx.x * BN;
    const int warp = t >> 5, lane = t & 31;
    const int wm = warp >> 2, wn = warp & 3;       // 4x4 warp grid
    const int g = lane >> 2, q = lane & 3;

    const uint32_t sbase = (uint32_t)__cvta_generic_to_shared(smem);

    auto load_tile = [&](int kt, int s) {
        uint32_t ab = sbase + (uint32_t)(s * (STAGE * 4));
        uint32_t bb = ab + (uint32_t)(A_STAGE * 4);
        const float* Ag = g_h + (size_t)m0 * HD + kt * BK;
        const float* Bg = g_w2r + (size_t)(kt * BK) * HD + n0;
#pragma unroll
        for (int i = 0; i < 2; i++) {              // A tile: 128x32
            int id = t + i * 512;
            int row = id >> 3, c4 = (id & 7) << 2;
            asm volatile("cp.async.cg.shared.global [%0], [%1], 16;\n"
                :: "r"(ab + (uint32_t)((row * ASTRIDE + c4) * 4)),
                   "l"(Ag + (size_t)row * HD + c4));
        }
#pragma unroll
        for (int i = 0; i < 4; i++) {              // B tile: 32x256
            int id = t + i * 512;
            int row = id >> 6, c4 = (id & 63) << 2;
            asm volatile("cp.async.cg.shared.global [%0], [%1], 16;\n"
                :: "r"(bb + (uint32_t)((row * BSTRIDE + c4) * 4)),
                   "l"(Bg + (size_t)row * HD + c4));
        }
        asm volatile("cp.async.commit_group;\n" ::: "memory");
    };

    // acc init = b2[col] (theta = h@w2 + b2)
    float acc[2][8][4];
#pragma unroll
    for (int nt = 0; nt < 8; nt++) {
        int col = n0 + wn * 64 + nt * 8 + q * 2;
        float ba = __ldg(b2 + col), bb2 = __ldg(b2 + col + 1);
#pragma unroll
        for (int mt = 0; mt < 2; mt++) {
            acc[mt][nt][0] = ba;  acc[mt][nt][1] = bb2;
            acc[mt][nt][2] = ba;  acc[mt][nt][3] = bb2;
        }
    }

    const int KT = HD / BK;   // 128
    load_tile(0, 0);

    for (int kt = 0; kt < KT; kt++) {
        asm volatile("cp.async.wait_group 0;\n" ::: "memory");
        __syncthreads();
        if (kt + 1 < KT) load_tile(kt + 1, (kt + 1) & 1);

        const float* a = smem + (kt & 1) * STAGE;
        const float* b = a + A_STAGE;

#pragma unroll
        for (int ks = 0; ks < 4; ks++) {
            const int k0 = ks * 8;
            uint32_t af[2][4];
#pragma unroll
            for (int mt = 0; mt < 2; mt++) {
                int r0 = wm * 32 + mt * 16 + g;
                af[mt][0] = __float_as_uint(a[r0 * ASTRIDE + k0 + q]);
                af[mt][1] = __float_as_uint(a[(r0 + 8) * ASTRIDE + k0 + q]);
                af[mt][2] = __float_as_uint(a[r0 * ASTRIDE + k0 + q + 4]);
                af[mt][3] = __float_as_uint(a[(r0 + 8) * ASTRIDE + k0 + q + 4]);
            }
            uint32_t bf[8][2];
#pragma unroll
            for (int nt = 0; nt < 8; nt++) {
                int c = wn * 64 + nt * 8 + g;
                bf[nt][0] = __float_as_uint(b[(k0 + q) * BSTRIDE + c]);
                bf[nt][1] = __float_as_uint(b[(k0 + q + 4) * BSTRIDE + c]);
            }
#pragma unroll
            for (int mt = 0; mt < 2; mt++)
#pragma unroll
                for (int nt = 0; nt < 8; nt++) {
                    asm volatile(
                        "mma.sync.aligned.m16n8k8.row.col.f32.tf32.tf32.f32 "
                        "{%0,%1,%2,%3}, {%4,%5,%6,%7}, {%8,%9}, {%0,%1,%2,%3};\n"
                        : "+f"(acc[mt][nt][0]), "+f"(acc[mt][nt][1]),
                          "+f"(acc[mt][nt][2]), "+f"(acc[mt][nt][3])
                        : "r"(af[mt][0]), "r"(af[mt][1]),
                          "r"(af[mt][2]), "r"(af[mt][3]),
                          "r"(bf[nt][0]), "r"(bf[nt][1]));
                }
        }
    }

    // Fused epilogue: msg[e,o] contribution for this warp's single channel i_w,
    // scattered straight into g_agg[dst]. o = nt*8 + q*2 (col & 63).
    const int i_w = (n0 >> 6) + wn;
#pragma unroll
    for (int mt = 0; mt < 2; mt++) {
#pragma unroll
        for (int hh = 0; hh < 2; hh++) {
            int e = m0 + wm * 32 + mt * 16 + g + hh * 8;
            int src = __ldg(ei + e);
            int dst = __ldg(ei + N_EDGES + e);
            float xv = __ldg(xin + src * DIM + i_w);
            float* aggp = g_agg + dst * DIM;
#pragma unroll
            for (int nt = 0; nt < 8; nt++) {
                int o = nt * 8 + q * 2;
                atomicAdd(aggp + o,     xv * acc[mt][nt][2 * hh]);
                atomicAdd(aggp + o + 1, xv * acc[mt][nt][2 * hh + 1]);
            }
        }
    }
}

// ---------------------------------------------------------------------------
// out[v] = relu(agg[v]/max(cnt,1) + x[v] @ root + bias); one warp per node
// ---------------------------------------------------------------------------
__global__ void node_update_kernel(const float* __restrict__ x,
                                   const float* __restrict__ root,
                                   const float* __restrict__ bias,
                                   float* __restrict__ out) {
    int v = (blockIdx.x * blockDim.x + threadIdx.x) >> 5;
    int lane = threadIdx.x & 31;
    if (v >= N_NODES) return;
    float inv = 1.0f / fmaxf(g_cnt[v], 1.0f);
    float a0 = g_agg[v * DIM + lane] * inv + __ldg(bias + lane);
    float a1 = g_agg[v * DIM + 32 + lane] * inv + __ldg(bias + 32 + lane);
    float xv0 = x[v * DIM + lane];
    float xv1 = x[v * DIM + 32 + lane];
#pragma unroll 8
    for (int i = 0; i < 32; i++) {
        float xi = __shfl_sync(0xffffffffu, xv0, i);
        a0 += xi * __ldg(root + i * 64 + lane);
        a1 += xi * __ldg(root + i * 64 + 32 + lane);
    }
#pragma unroll 8
    for (int i = 0; i < 32; i++) {
        float xi = __shfl_sync(0xffffffffu, xv1, i);
        a0 += xi * __ldg(root + (32 + i) * 64 + lane);
        a1 += xi * __ldg(root + (32 + i) * 64 + 32 + lane);
    }
    out[v * DIM + lane] = fmaxf(a0, 0.0f);
    out[v * DIM + 32 + lane] = fmaxf(a1, 0.0f);
}

// ---------------------------------------------------------------------------
// Global mean pool
// ---------------------------------------------------------------------------
__global__ void pool_sum_kernel(const float* __restrict__ y,
                                const int* __restrict__ batch,
                                float* __restrict__ out) {
    int v = (blockIdx.x * blockDim.x + threadIdx.x) >> 5;
    int lane = threadIdx.x & 31;
    if (v >= N_NODES) return;
    int gr = batch[v];
    atomicAdd(&out[gr * DIM + lane], y[v * DIM + lane]);
    atomicAdd(&out[gr * DIM + 32 + lane], y[v * DIM + 32 + lane]);
    if (lane == 0) atomicAdd(&g_gcnt[gr], 1.0f);
}

__global__ void pool_div_kernel(float* __restrict__ out) {
    int i = blockIdx.x * blockDim.x + threadIdx.x;
    if (i < N_GRAPHS * DIM) out[i] /= fmaxf(g_gcnt[i / DIM], 1.0f);
}

// ---------------------------------------------------------------------------
// Launch
// ---------------------------------------------------------------------------
extern "C" void kernel_launch(void* const* d_in, const int* in_sizes, int n_in,
                              void* d_out, int out_size) {
    (void)in_sizes; (void)n_in; (void)out_size;
    const float* x     = (const float*)d_in[0];
    const int*   ei    = (const int*)d_in[1];
    const float* ea    = (const float*)d_in[2];
    const int*   batch = (const int*)d_in[3];
    const float* W[3][6];
    for (int l = 0; l < 3; l++)
        for (int j = 0; j < 6; j++)
            W[l][j] = (const float*)d_in[4 + l * 6 + j];   // w1,b1,w2,b2,root,bias
    float* out = (float*)d_out;

    cudaFuncSetAttribute(gemm_scatter_kernel,
                         cudaFuncAttributeMaxDynamicSharedMemorySize, SMEM_BYTES);

    float *p_cnt, *p_agg, *p_feat, *p_gcnt;
    cudaGetSymbolAddress((void**)&p_cnt,  g_cnt);
    cudaGetSymbolAddress((void**)&p_agg,  g_agg);
    cudaGetSymbolAddress((void**)&p_feat, g_feat);
    cudaGetSymbolAddress((void**)&p_gcnt, g_gcnt);

    zero_kernel<<<(N_NODES + 255) / 256, 256>>>(p_cnt, N_NODES);
    cnt_kernel<<<(N_EDGES + 255) / 256, 256>>>(ei);

    const float* xin = x;
    for (int l = 0; l < 3; l++) {
        float* xout = p_feat + (l & 1) * (N_NODES * DIM);

        dim3 gmlp(N_EDGES / 32, HD / 128);
        edge_mlp_kernel<<<gmlp, 256>>>(ea, W[l][0], W[l][1]);

        round_w2_kernel<<<(HD * HD / 4) / 256, 256>>>(W[l][2]);

        zero_kernel<<<(N_NODES * DIM + 255) / 256, 256>>>(p_agg, N_NODES * DIM);

        dim3 gg(HD / BN, N_EDGES / BM);   // (16, 128)
        gemm_scatter_kernel<<<gg, 512, SMEM_BYTES>>>(W[l][3], xin, ei);

        node_update_kernel<<<N_NODES / 8, 256>>>(xin, W[l][4], W[l][5], xout);
        xin = xout;
    }

    zero_kernel<<<(N_GRAPHS * DIM + 255) / 256, 256>>>(out, N_GRAPHS * DIM);
    zero_kernel<<<1, 256>>>(p_gcnt, N_GRAPHS);
    pool_sum_kernel<<<N_NODES / 8, 256>>>(xin, batch, out);
    pool_div_kernel<<<(N_GRAPHS * DIM + 255) / 256, 256>>>(out);
}

// round 8
// speedup vs baseline: 1.0678x; 1.0678x over previous
#include <cuda_runtime.h>
#include <cstdint>

#define N_NODES  4096
#define N_EDGES  16384
#define N_GRAPHS 128
#define DIM      64     // IN = H = 64 for all layers
#define EDIM     16
#define HD       4096   // DIM*DIM, edge-MLP width

// ---------------------------------------------------------------------------
// Scratch (static __device__ globals: no allocation anywhere)
// ---------------------------------------------------------------------------
__device__ float g_h[N_EDGES * HD];       // 268 MB: relu(ea@w1+b1), tf32-rounded
__device__ float g_theta[N_EDGES * HD];   // 268 MB: h@w2 + b2
__device__ float g_w2r[HD * HD];          // 64 MB: tf32-rounded w2 [K,N]
__device__ float g_feat[2][N_NODES * DIM];
__device__ float g_agg[N_NODES * DIM];
__device__ float g_cnt[N_NODES];
__device__ float g_gcnt[N_GRAPHS];

__device__ __forceinline__ uint32_t f2tf32(float x) {
    uint32_t r;
    asm("cvt.rna.tf32.f32 %0, %1;" : "=r"(r) : "f"(x));
    return r;
}

// ---------------------------------------------------------------------------
// Utility kernels
// ---------------------------------------------------------------------------
__global__ void zero_kernel(float* __restrict__ p, int n) {
    int i = blockIdx.x * blockDim.x + threadIdx.x;
    if (i < n) p[i] = 0.0f;
}

__global__ void cnt_kernel(const int* __restrict__ ei) {
    int e = blockIdx.x * blockDim.x + threadIdx.x;
    if (e < N_EDGES) atomicAdd(&g_cnt[ei[N_EDGES + e]], 1.0f);
}

// w2 -> tf32-rounded copy (removes cvt from GEMM inner loop)
__global__ void round_w2_kernel(const float* __restrict__ w2) {
    int i = blockIdx.x * blockDim.x + threadIdx.x;   // float4 index
    float4 v = *reinterpret_cast<const float4*>(w2 + (size_t)i * 4);
    uint4 r;
    r.x = f2tf32(v.x); r.y = f2tf32(v.y); r.z = f2tf32(v.z); r.w = f2tf32(v.w);
    *reinterpret_cast<uint4*>(g_w2r + (size_t)i * 4) = r;
}

// ---------------------------------------------------------------------------
// h = relu(edge_attr @ w1 + b1), stored tf32-rounded.
// ---------------------------------------------------------------------------
__global__ void edge_mlp_kernel(const float* __restrict__ ea,
                                const float* __restrict__ w1,
                                const float* __restrict__ b1) {
    __shared__ float sa[32][20];
    __shared__ float sw[16][128];
    const int e0 = blockIdx.x * 32;
    const int c0 = blockIdx.y * 128;
    const int t  = threadIdx.x;

    if (t < 128) {
        int e = t >> 2, d4 = (t & 3) << 2;
        float4 v = *reinterpret_cast<const float4*>(ea + (e0 + e) * EDIM + d4);
        *reinterpret_cast<float4*>(&sa[e][d4]) = v;
    }
#pragma unroll
    for (int i = 0; i < 2; i++) {
        int id = t + i * 256;
        int d = id >> 5, c4 = (id & 31) << 2;
        float4 v = *reinterpret_cast<const float4*>(w1 + d * HD + c0 + c4);
        *reinterpret_cast<float4*>(&sw[d][c4]) = v;
    }
    __syncthreads();

    const int lc = t & 127;
    const int eh = t >> 7;
    float wreg[16];
#pragma unroll
    for (int d = 0; d < 16; d++) wreg[d] = sw[d][lc];
    const float bias = __ldg(b1 + c0 + lc);

#pragma unroll
    for (int j = 0; j < 16; j++) {
        int e = eh + j * 2;
        float acc = bias;
#pragma unroll
        for (int d = 0; d < 16; d++) acc += sa[e][d] * wreg[d];
        acc = fmaxf(acc, 0.0f);
        g_h[(size_t)(e0 + e) * HD + c0 + lc] = __uint_as_float(f2tf32(acc));
    }
}

// ---------------------------------------------------------------------------
// theta = g_h @ g_w2r + b2   [M=16384, N=4096, K=4096], TF32 mma.sync.
// BM=128 BN=128 BK=32, 2-stage cp.async, 256 threads, 2 CTAs/SM.
// Warp grid 2x4, warp tile 64x32 (4 m-tiles x 4 n-tiles of m16n8k8).
// acc=64 regs/thread -> fits 128-reg cap at occupancy 2 without spill.
// Smem strides: A=36 (banks 4g+q), B=136 (banks 8q+g) -> conflict-free.
// ---------------------------------------------------------------------------
#define BM 128
#define BN 128
#define BK 32
#define ASTRIDE 36
#define BSTRIDE 136
#define A_STAGE (BM * ASTRIDE)            // 4608 floats
#define B_STAGE (BK * BSTRIDE)            // 4352 floats
#define STAGE   (A_STAGE + B_STAGE)       // 8960 floats
#define SMEM_BYTES (2 * STAGE * 4)        // 71680 B

__global__ __launch_bounds__(256, 2)
void gemm_tf32_kernel(const float* __restrict__ b2) {
    extern __shared__ float smem[];
    const int t  = threadIdx.x;
    const int m0 = blockIdx.y * BM;
    const int n0 = blockIdx.x * BN;
    const int warp = t >> 5, lane = t & 31;
    const int wm = warp >> 2, wn = warp & 3;      // 2x4 warp grid
    const int g = lane >> 2, q = lane & 3;

    const uint32_t sbase = (uint32_t)__cvta_generic_to_shared(smem);

    auto load_tile = [&](int kt, int s) {
        uint32_t ab = sbase + (uint32_t)(s * (STAGE * 4));
        uint32_t bb = ab + (uint32_t)(A_STAGE * 4);
        const float* Ag = g_h + (size_t)m0 * HD + kt * BK;
        const float* Bg = g_w2r + (size_t)(kt * BK) * HD + n0;
#pragma unroll
        for (int i = 0; i < 4; i++) {              // A tile: 128x32
            int id = t + i * 256;
            int row = id >> 3, c4 = (id & 7) << 2;
            asm volatile("cp.async.cg.shared.global [%0], [%1], 16;\n"
                :: "r"(ab + (uint32_t)((row * ASTRIDE + c4) * 4)),
                   "l"(Ag + (size_t)row * HD + c4));
        }
#pragma unroll
        for (int i = 0; i < 4; i++) {              // B tile: 32x128
            int id = t + i * 256;
            int row = id >> 5, c4 = (id & 31) << 2;
            asm volatile("cp.async.cg.shared.global [%0], [%1], 16;\n"
                :: "r"(bb + (uint32_t)((row * BSTRIDE + c4) * 4)),
                   "l"(Bg + (size_t)row * HD + c4));
        }
        asm volatile("cp.async.commit_group;\n" ::: "memory");
    };

    float acc[4][4][4];
#pragma unroll
    for (int mt = 0; mt < 4; mt++)
#pragma unroll
        for (int nt = 0; nt < 4; nt++)
#pragma unroll
            for (int r = 0; r < 4; r++) acc[mt][nt][r] = 0.0f;

    const int KT = HD / BK;   // 128
    load_tile(0, 0);

    for (int kt = 0; kt < KT; kt++) {
        asm volatile("cp.async.wait_group 0;\n" ::: "memory");
        __syncthreads();
        if (kt + 1 < KT) load_tile(kt + 1, (kt + 1) & 1);

        const float* a = smem + (kt & 1) * STAGE;
        const float* b = a + A_STAGE;

#pragma unroll
        for (int ks = 0; ks < 4; ks++) {
            const int k0 = ks * 8;
            uint32_t af[4][4];
#pragma unroll
            for (int mt = 0; mt < 4; mt++) {
                int r0 = wm * 64 + mt * 16 + g;
                af[mt][0] = __float_as_uint(a[r0 * ASTRIDE + k0 + q]);
                af[mt][1] = __float_as_uint(a[(r0 + 8) * ASTRIDE + k0 + q]);
                af[mt][2] = __float_as_uint(a[r0 * ASTRIDE + k0 + q + 4]);
                af[mt][3] = __float_as_uint(a[(r0 + 8) * ASTRIDE + k0 + q + 4]);
            }
            uint32_t bf[4][2];
#pragma unroll
            for (int nt = 0; nt < 4; nt++) {
                int c = wn * 32 + nt * 8 + g;
                bf[nt][0] = __float_as_uint(b[(k0 + q) * BSTRIDE + c]);
                bf[nt][1] = __float_as_uint(b[(k0 + q + 4) * BSTRIDE + c]);
            }
#pragma unroll
            for (int mt = 0; mt < 4; mt++)
#pragma unroll
                for (int nt = 0; nt < 4; nt++) {
                    asm volatile(
                        "mma.sync.aligned.m16n8k8.row.col.f32.tf32.tf32.f32 "
                        "{%0,%1,%2,%3}, {%4,%5,%6,%7}, {%8,%9}, {%0,%1,%2,%3};\n"
                        : "+f"(acc[mt][nt][0]), "+f"(acc[mt][nt][1]),
                          "+f"(acc[mt][nt][2]), "+f"(acc[mt][nt][3])
                        : "r"(af[mt][0]), "r"(af[mt][1]),
                          "r"(af[mt][2]), "r"(af[mt][3]),
                          "r"(bf[nt][0]), "r"(bf[nt][1]));
                }
        }
    }

    // epilogue: + b2, write theta
#pragma unroll
    for (int mt = 0; mt < 4; mt++) {
        int row = m0 + wm * 64 + mt * 16 + g;
#pragma unroll
        for (int nt = 0; nt < 4; nt++) {
            int col = n0 + wn * 32 + nt * 8 + q * 2;
            float ba = __ldg(b2 + col), bb2 = __ldg(b2 + col + 1);
            float2 v0 = make_float2(acc[mt][nt][0] + ba, acc[mt][nt][1] + bb2);
            float2 v1 = make_float2(acc[mt][nt][2] + ba, acc[mt][nt][3] + bb2);
            *reinterpret_cast<float2*>(&g_theta[(size_t)row * HD + col]) = v0;
            *reinterpret_cast<float2*>(&g_theta[(size_t)(row + 8) * HD + col]) = v1;
        }
    }
}

// ---------------------------------------------------------------------------
// msg[e,o] = sum_i x[src_e,i] * theta[e, i*64+o]; scatter-add into g_agg[dst]
// ---------------------------------------------------------------------------
__global__ void msg_kernel(const float* __restrict__ x,
                           const int* __restrict__ ei) {
    int e = (blockIdx.x * blockDim.x + threadIdx.x) >> 5;
    int lane = threadIdx.x & 31;
    if (e >= N_EDGES) return;
    int src = ei[e];
    int dst = ei[N_EDGES + e];
    float xv0 = x[src * DIM + lane];
    float xv1 = x[src * DIM + 32 + lane];
    const float* th = g_theta + (size_t)e * HD;
    float a0 = 0.0f, a1 = 0.0f;
#pragma unroll 8
    for (int i = 0; i < 32; i++) {
        float xi = __shfl_sync(0xffffffffu, xv0, i);
        a0 += xi * th[i * 64 + lane];
        a1 += xi * th[i * 64 + 32 + lane];
    }
#pragma unroll 8
    for (int i = 0; i < 32; i++) {
        float xi = __shfl_sync(0xffffffffu, xv1, i);
        a0 += xi * th[(32 + i) * 64 + lane];
        a1 += xi * th[(32 + i) * 64 + 32 + lane];
    }
    atomicAdd(&g_agg[dst * DIM + lane], a0);
    atomicAdd(&g_agg[dst * DIM + 32 + lane], a1);
}

// ---------------------------------------------------------------------------
// out[v] = relu(agg[v]/max(cnt,1) + x[v] @ root + bias); one warp per node
// ---------------------------------------------------------------------------
__global__ void node_update_kernel(const float* __restrict__ x,
                                   const float* __restrict__ root,
                                   const float* __restrict__ bias,
                                   float* __restrict__ out) {
    int v = (blockIdx.x * blockDim.x + threadIdx.x) >> 5;
    int lane = threadIdx.x & 31;
    if (v >= N_NODES) return;
    float inv = 1.0f / fmaxf(g_cnt[v], 1.0f);
    float a0 = g_agg[v * DIM + lane] * inv + __ldg(bias + lane);
    float a1 = g_agg[v * DIM + 32 + lane] * inv + __ldg(bias + 32 + lane);
    float xv0 = x[v * DIM + lane];
    float xv1 = x[v * DIM + 32 + lane];
#pragma unroll 8
    for (int i = 0; i < 32; i++) {
        float xi = __shfl_sync(0xffffffffu, xv0, i);
        a0 += xi * __ldg(root + i * 64 + lane);
        a1 += xi * __ldg(root + i * 64 + 32 + lane);
    }
#pragma unroll 8
    for (int i = 0; i < 32; i++) {
        float xi = __shfl_sync(0xffffffffu, xv1, i);
        a0 += xi * __ldg(root + (32 + i) * 64 + lane);
        a1 += xi * __ldg(root + (32 + i) * 64 + 32 + lane);
    }
    out[v * DIM + lane] = fmaxf(a0, 0.0f);
    out[v * DIM + 32 + lane] = fmaxf(a1, 0.0f);
}

// ---------------------------------------------------------------------------
// Global mean pool
// ---------------------------------------------------------------------------
__global__ void pool_sum_kernel(const float* __restrict__ y,
                                const int* __restrict__ batch,
                                float* __restrict__ out) {
    int v = (blockIdx.x * blockDim.x + threadIdx.x) >> 5;
    int lane = threadIdx.x & 31;
    if (v >= N_NODES) return;
    int gr = batch[v];
    atomicAdd(&out[gr * DIM + lane], y[v * DIM + lane]);
    atomicAdd(&out[gr * DIM + 32 + lane], y[v * DIM + 32 + lane]);
    if (lane == 0) atomicAdd(&g_gcnt[gr], 1.0f);
}

__global__ void pool_div_kernel(float* __restrict__ out) {
    int i = blockIdx.x * blockDim.x + threadIdx.x;
    if (i < N_GRAPHS * DIM) out[i] /= fmaxf(g_gcnt[i / DIM], 1.0f);
}

// ---------------------------------------------------------------------------
// Launch
// ---------------------------------------------------------------------------
extern "C" void kernel_launch(void* const* d_in, const int* in_sizes, int n_in,
                              void* d_out, int out_size) {
    (void)in_sizes; (void)n_in; (void)out_size;
    const float* x     = (const float*)d_in[0];
    const int*   ei    = (const int*)d_in[1];
    const float* ea    = (const float*)d_in[2];
    const int*   batch = (const int*)d_in[3];
    const float* W[3][6];
    for (int l = 0; l < 3; l++)
        for (int j = 0; j < 6; j++)
            W[l][j] = (const float*)d_in[4 + l * 6 + j];   // w1,b1,w2,b2,root,bias
    float* out = (float*)d_out;

    cudaFuncSetAttribute(gemm_tf32_kernel,
                         cudaFuncAttributeMaxDynamicSharedMemorySize, SMEM_BYTES);

    float *p_cnt, *p_agg, *p_feat, *p_gcnt;
    cudaGetSymbolAddress((void**)&p_cnt,  g_cnt);
    cudaGetSymbolAddress((void**)&p_agg,  g_agg);
    cudaGetSymbolAddress((void**)&p_feat, g_feat);
    cudaGetSymbolAddress((void**)&p_gcnt, g_gcnt);

    zero_kernel<<<(N_NODES + 255) / 256, 256>>>(p_cnt, N_NODES);
    cnt_kernel<<<(N_EDGES + 255) / 256, 256>>>(ei);

    const float* xin = x;
    for (int l = 0; l < 3; l++) {
        float* xout = p_feat + (l & 1) * (N_NODES * DIM);

        dim3 gmlp(N_EDGES / 32, HD / 128);
        edge_mlp_kernel<<<gmlp, 256>>>(ea, W[l][0], W[l][1]);

        round_w2_kernel<<<(HD * HD / 4) / 256, 256>>>(W[l][2]);

        dim3 gg(HD / BN, N_EDGES / BM);   // (32, 128)
        gemm_tf32_kernel<<<gg, 256, SMEM_BYTES>>>(W[l][3]);

        zero_kernel<<<(N_NODES * DIM + 255) / 256, 256>>>(p_agg, N_NODES * DIM);
        msg_kernel<<<N_EDGES / 8, 256>>>(xin, ei);
        node_update_kernel<<<N_NODES / 8, 256>>>(xin, W[l][4], W[l][5], xout);
        xin = xout;
    }

    zero_kernel<<<(N_GRAPHS * DIM + 255) / 256, 256>>>(out, N_GRAPHS * DIM);
    zero_kernel<<<1, 256>>>(p_gcnt, N_GRAPHS);
    pool_sum_kernel<<<N_NODES / 8, 256>>>(xin, batch, out);
    pool_div_kernel<<<(N_GRAPHS * DIM + 255) / 256, 256>>>(out);
}

// round 11
// speedup vs baseline: 1.6561x; 1.5510x over previous
#include <cuda_runtime.h>
#include <cuda_fp16.h>
#include <cstdint>

#define N_NODES  4096
#define N_EDGES  16384
#define N_GRAPHS 128
#define DIM      64     // IN = H = 64 for all layers
#define EDIM     16
#define HD       4096   // DIM*DIM, edge-MLP width

// ---------------------------------------------------------------------------
// Scratch (static __device__ globals: no allocation anywhere)
// ---------------------------------------------------------------------------
__device__ __half g_h[N_EDGES * HD];      // 134 MB: relu(ea@w1+b1) in fp16
__device__ __half g_w2h[HD * HD];         // 32 MB: w2 transposed [N,K] in fp16
__device__ float  g_theta[N_EDGES * HD];  // 268 MB: h@w2 + b2
__device__ float  g_feat[2][N_NODES * DIM];
__device__ float  g_agg[N_NODES * DIM];
__device__ float  g_cnt[N_NODES];
__device__ float  g_gcnt[N_GRAPHS];

// ---------------------------------------------------------------------------
// Utility kernels
// ---------------------------------------------------------------------------
__global__ void zero_kernel(float* __restrict__ p, int n) {
    int i = blockIdx.x * blockDim.x + threadIdx.x;
    if (i < n) p[i] = 0.0f;
}

__global__ void cnt_kernel(const int* __restrict__ ei) {
    int e = blockIdx.x * blockDim.x + threadIdx.x;
    if (e < N_EDGES) atomicAdd(&g_cnt[ei[N_EDGES + e]], 1.0f);
}

// w2 [K,N] fp32 -> g_w2h [N,K] fp16 (B operand, K-contiguous)
__global__ void round_w2T_kernel(const float* __restrict__ w2) {
    __shared__ float tile[32][33];
    int k0 = blockIdx.y * 32, nn0 = blockIdx.x * 32;
    int tx = threadIdx.x, ty = threadIdx.y;  // (32,8)
#pragma unroll
    for (int r = 0; r < 4; r++)
        tile[ty + 8 * r][tx] = w2[(size_t)(k0 + ty + 8 * r) * HD + nn0 + tx];
    __syncthreads();
#pragma unroll
    for (int r = 0; r < 4; r++)
        g_w2h[(size_t)(nn0 + ty + 8 * r) * HD + k0 + tx] =
            __float2half_rn(tile[tx][ty + 8 * r]);
}

// ---------------------------------------------------------------------------
// h = relu(edge_attr @ w1 + b1), stored fp16 (A operand).
// ---------------------------------------------------------------------------
__global__ void edge_mlp_kernel(const float* __restrict__ ea,
                                const float* __restrict__ w1,
                                const float* __restrict__ b1) {
    __shared__ float sa[32][20];
    __shared__ float sw[16][128];
    const int e0 = blockIdx.x * 32;
    const int c0 = blockIdx.y * 128;
    const int t  = threadIdx.x;

    if (t < 128) {
        int e = t >> 2, d4 = (t & 3) << 2;
        float4 v = *reinterpret_cast<const float4*>(ea + (e0 + e) * EDIM + d4);
        *reinterpret_cast<float4*>(&sa[e][d4]) = v;
    }
#pragma unroll
    for (int i = 0; i < 2; i++) {
        int id = t + i * 256;
        int d = id >> 5, c4 = (id & 31) << 2;
        float4 v = *reinterpret_cast<const float4*>(w1 + d * HD + c0 + c4);
        *reinterpret_cast<float4*>(&sw[d][c4]) = v;
    }
    __syncthreads();

    const int lc = t & 127;
    const int eh = t >> 7;
    float wreg[16];
#pragma unroll
    for (int d = 0; d < 16; d++) wreg[d] = sw[d][lc];
    const float bias = __ldg(b1 + c0 + lc);

#pragma unroll
    for (int j = 0; j < 16; j++) {
        int e = eh + j * 2;
        float acc = bias;
#pragma unroll
        for (int d = 0; d < 16; d++) acc += sa[e][d] * wreg[d];
        acc = fmaxf(acc, 0.0f);
        g_h[(size_t)(e0 + e) * HD + c0 + lc] = __float2half_rn(acc);
    }
}

// ---------------------------------------------------------------------------
// theta = g_h @ g_w2h^T + b2   [M=16384, N=4096, K=4096], FP16 mma m16n8k16.
// BM=128 BN=128 BK=32, 2-stage cp.async, 256 threads, 2 CTAs/SM.
// Warp grid 2x4, warp tile 64x32 (4 m-tiles x 4 n-tiles of m16n8k16).
// A tile [128m x 32k] halfs, B tile [128n x 32k] halfs, both stride 40 halfs
// (20 words): fragment banks = 4*(5g mod 8)+q -> conflict-free permutation.
// acc=64 regs/thread; fits 128-reg cap at occupancy 2.
// ---------------------------------------------------------------------------
#define BM 128
#define BN 128
#define BK 32
#define STR_H 40                           // halfs per row (80 B)
#define STR_W 20                           // 32-bit words per row
#define A_STAGE_W (BM * STR_W)             // 2560 words
#define B_STAGE_W (BN * STR_W)             // 2560 words
#define STAGE_W   (A_STAGE_W + B_STAGE_W)  // 5120 words
#define SMEM_BYTES (2 * STAGE_W * 4)       // 40960 B

__global__ __launch_bounds__(256, 2)
void gemm_fp16_kernel(const float* __restrict__ b2) {
    extern __shared__ uint32_t smem[];
    const int t  = threadIdx.x;
    const int m0 = blockIdx.y * BM;
    const int n0 = blockIdx.x * BN;
    const int warp = t >> 5, lane = t & 31;
    const int wm = warp >> 2, wn = warp & 3;      // 2x4 warp grid
    const int g = lane >> 2, q = lane & 3;

    const uint32_t sbase = (uint32_t)__cvta_generic_to_shared(smem);

    auto load_tile = [&](int kt, int s) {
        uint32_t ab = sbase + (uint32_t)(s * (STAGE_W * 4));
        uint32_t bb = ab + (uint32_t)(A_STAGE_W * 4);
#pragma unroll
        for (int i = 0; i < 2; i++) {              // A tile: 128 rows x 4 x 16B
            int c = t + i * 256;
            int row = c >> 2, ch = c & 3;
            const char* src = (const char*)(g_h + (size_t)(m0 + row) * HD + kt * BK) + ch * 16;
            asm volatile("cp.async.cg.shared.global [%0], [%1], 16;\n"
                :: "r"(ab + (uint32_t)(row * 80 + ch * 16)), "l"(src));
        }
#pragma unroll
        for (int i = 0; i < 2; i++) {              // B tile: 128 rows x 4 x 16B
            int c = t + i * 256;
            int row = c >> 2, ch = c & 3;
            const char* src = (const char*)(g_w2h + (size_t)(n0 + row) * HD + kt * BK) + ch * 16;
            asm volatile("cp.async.cg.shared.global [%0], [%1], 16;\n"
                :: "r"(bb + (uint32_t)(row * 80 + ch * 16)), "l"(src));
        }
        asm volatile("cp.async.commit_group;\n" ::: "memory");
    };

    float acc[4][4][4];
#pragma unroll
    for (int mt = 0; mt < 4; mt++)
#pragma unroll
        for (int nt = 0; nt < 4; nt++)
#pragma unroll
            for (int r = 0; r < 4; r++) acc[mt][nt][r] = 0.0f;

    const int KT = HD / BK;   // 128
    load_tile(0, 0);

    for (int kt = 0; kt < KT; kt++) {
        asm volatile("cp.async.wait_group 0;\n" ::: "memory");
        __syncthreads();
        if (kt + 1 < KT) load_tile(kt + 1, (kt + 1) & 1);

        const uint32_t* a = smem + (kt & 1) * STAGE_W;
        const uint32_t* b = a + A_STAGE_W;

#pragma unroll
        for (int ks = 0; ks < 2; ks++) {          // two k16 steps per BK=32
            const int kw = ks * 8;                 // word offset within row
            uint32_t af[4][4];
#pragma unroll
            for (int mt = 0; mt < 4; mt++) {
                int r0 = wm * 64 + mt * 16 + g;
                af[mt][0] = a[r0 * STR_W + kw + q];
                af[mt][1] = a[(r0 + 8) * STR_W + kw + q];
                af[mt][2] = a[r0 * STR_W + kw + 4 + q];
                af[mt][3] = a[(r0 + 8) * STR_W + kw + 4 + q];
            }
            uint32_t bf[4][2];
#pragma unroll
            for (int nt = 0; nt < 4; nt++) {
                int nr = wn * 32 + nt * 8 + g;
                bf[nt][0] = b[nr * STR_W + kw + q];
                bf[nt][1] = b[nr * STR_W + kw + 4 + q];
            }
#pragma unroll
            for (int mt = 0; mt < 4; mt++)
#pragma unroll
                for (int nt = 0; nt < 4; nt++) {
                    asm volatile(
                        "mma.sync.aligned.m16n8k16.row.col.f32.f16.f16.f32 "
                        "{%0,%1,%2,%3}, {%4,%5,%6,%7}, {%8,%9}, {%0,%1,%2,%3};\n"
                        : "+f"(acc[mt][nt][0]), "+f"(acc[mt][nt][1]),
                          "+f"(acc[mt][nt][2]), "+f"(acc[mt][nt][3])
                        : "r"(af[mt][0]), "r"(af[mt][1]),
                          "r"(af[mt][2]), "r"(af[mt][3]),
                          "r"(bf[nt][0]), "r"(bf[nt][1]));
                }
        }
    }

    // epilogue: + b2, write theta (fp32)
#pragma unroll
    for (int mt = 0; mt < 4; mt++) {
        int row = m0 + wm * 64 + mt * 16 + g;
#pragma unroll
        for (int nt = 0; nt < 4; nt++) {
            int col = n0 + wn * 32 + nt * 8 + q * 2;
            float ba = __ldg(b2 + col), bb2 = __ldg(b2 + col + 1);
            float2 v0 = make_float2(acc[mt][nt][0] + ba, acc[mt][nt][1] + bb2);
            float2 v1 = make_float2(acc[mt][nt][2] + ba, acc[mt][nt][3] + bb2);
            *reinterpret_cast<float2*>(&g_theta[(size_t)row * HD + col]) = v0;
            *reinterpret_cast<float2*>(&g_theta[(size_t)(row + 8) * HD + col]) = v1;
        }
    }
}

// ---------------------------------------------------------------------------
// msg[e,o] = sum_i x[src_e,i] * theta[e, i*64+o]; scatter-add into g_agg[dst]
// ---------------------------------------------------------------------------
__global__ void msg_kernel(const float* __restrict__ x,
                           const int* __restrict__ ei) {
    int e = (blockIdx.x * blockDim.x + threadIdx.x) >> 5;
    int lane = threadIdx.x & 31;
    if (e >= N_EDGES) return;
    int src = ei[e];
    int dst = ei[N_EDGES + e];
    float xv0 = x[src * DIM + lane];
    float xv1 = x[src * DIM + 32 + lane];
    const float* th = g_theta + (size_t)e * HD;
    float a0 = 0.0f, a1 = 0.0f;
#pragma unroll 8
    for (int i = 0; i < 32; i++) {
        float xi = __shfl_sync(0xffffffffu, xv0, i);
        a0 += xi * th[i * 64 + lane];
        a1 += xi * th[i * 64 + 32 + lane];
    }
#pragma unroll 8
    for (int i = 0; i < 32; i++) {
        float xi = __shfl_sync(0xffffffffu, xv1, i);
        a0 += xi * th[(32 + i) * 64 + lane];
        a1 += xi * th[(32 + i) * 64 + 32 + lane];
    }
    atomicAdd(&g_agg[dst * DIM + lane], a0);
    atomicAdd(&g_agg[dst * DIM + 32 + lane], a1);
}

// ---------------------------------------------------------------------------
// out[v] = relu(agg[v]/max(cnt,1) + x[v] @ root + bias); one warp per node
// ---------------------------------------------------------------------------
__global__ void node_update_kernel(const float* __restrict__ x,
                                   const float* __restrict__ root,
                                   const float* __restrict__ bias,
                                   float* __restrict__ out) {
    int v = (blockIdx.x * blockDim.x + threadIdx.x) >> 5;
    int lane = threadIdx.x & 31;
    if (v >= N_NODES) return;
    float inv = 1.0f / fmaxf(g_cnt[v], 1.0f);
    float a0 = g_agg[v * DIM + lane] * inv + __ldg(bias + lane);
    float a1 = g_agg[v * DIM + 32 + lane] * inv + __ldg(bias + 32 + lane);
    float xv0 = x[v * DIM + lane];
    float xv1 = x[v * DIM + 32 + lane];
#pragma unroll 8
    for (int i = 0; i < 32; i++) {
        float xi = __shfl_sync(0xffffffffu, xv0, i);
        a0 += xi * __ldg(root + i * 64 + lane);
        a1 += xi * __ldg(root + i * 64 + 32 + lane);
    }
#pragma unroll 8
    for (int i = 0; i < 32; i++) {
        float xi = __shfl_sync(0xffffffffu, xv1, i);
        a0 += xi * __ldg(root + (32 + i) * 64 + lane);
        a1 += xi * __ldg(root + (32 + i) * 64 + 32 + lane);
    }
    out[v * DIM + lane] = fmaxf(a0, 0.0f);
    out[v * DIM + 32 + lane] = fmaxf(a1, 0.0f);
}

// ---------------------------------------------------------------------------
// Global mean pool
// ---------------------------------------------------------------------------
__global__ void pool_sum_kernel(const float* __restrict__ y,
                                const int* __restrict__ batch,
                                float* __restrict__ out) {
    int v = (blockIdx.x * blockDim.x + threadIdx.x) >> 5;
    int lane = threadIdx.x & 31;
    if (v >= N_NODES) return;
    int gr = batch[v];
    atomicAdd(&out[gr * DIM + lane], y[v * DIM + lane]);
    atomicAdd(&out[gr * DIM + 32 + lane], y[v * DIM + 32 + lane]);
    if (lane == 0) atomicAdd(&g_gcnt[gr], 1.0f);
}

__global__ void pool_div_kernel(float* __restrict__ out) {
    int i = blockIdx.x * blockDim.x + threadIdx.x;
    if (i < N_GRAPHS * DIM) out[i] /= fmaxf(g_gcnt[i / DIM], 1.0f);
}

// ---------------------------------------------------------------------------
// Launch
// ---------------------------------------------------------------------------
extern "C" void kernel_launch(void* const* d_in, const int* in_sizes, int n_in,
                              void* d_out, int out_size) {
    (void)in_sizes; (void)n_in; (void)out_size;
    const float* x     = (const float*)d_in[0];
    const int*   ei    = (const int*)d_in[1];
    const float* ea    = (const float*)d_in[2];
    const int*   batch = (const int*)d_in[3];
    const float* W[3][6];
    for (int l = 0; l < 3; l++)
        for (int j = 0; j < 6; j++)
            W[l][j] = (const float*)d_in[4 + l * 6 + j];   // w1,b1,w2,b2,root,bias
    float* out = (float*)d_out;

    cudaFuncSetAttribute(gemm_fp16_kernel,
                         cudaFuncAttributeMaxDynamicSharedMemorySize, SMEM_BYTES);

    float *p_cnt, *p_agg, *p_feat, *p_gcnt;
    cudaGetSymbolAddress((void**)&p_cnt,  g_cnt);
    cudaGetSymbolAddress((void**)&p_agg,  g_agg);
    cudaGetSymbolAddress((void**)&p_feat, g_feat);
    cudaGetSymbolAddress((void**)&p_gcnt, g_gcnt);

    zero_kernel<<<(N_NODES + 255) / 256, 256>>>(p_cnt, N_NODES);
    cnt_kernel<<<(N_EDGES + 255) / 256, 256>>>(ei);

    const float* xin = x;
    for (int l = 0; l < 3; l++) {
        float* xout = p_feat + (l & 1) * (N_NODES * DIM);

        dim3 gmlp(N_EDGES / 32, HD / 128);
        edge_mlp_kernel<<<gmlp, 256>>>(ea, W[l][0], W[l][1]);

        round_w2T_kernel<<<dim3(HD / 32, HD / 32), dim3(32, 8)>>>(W[l][2]);

        dim3 gg(HD / BN, N_EDGES / BM);   // (32, 128)
        gemm_fp16_kernel<<<gg, 256, SMEM_BYTES>>>(W[l][3]);

        zero_kernel<<<(N_NODES * DIM + 255) / 256, 256>>>(p_agg, N_NODES * DIM);
        msg_kernel<<<N_EDGES / 8, 256>>>(xin, ei);
        node_update_kernel<<<N_NODES / 8, 256>>>(xin, W[l][4], W[l][5], xout);
        xin = xout;
    }

    zero_kernel<<<(N_GRAPHS * DIM + 255) / 256, 256>>>(out, N_GRAPHS * DIM);
    zero_kernel<<<1, 256>>>(p_gcnt, N_GRAPHS);
    pool_sum_kernel<<<N_NODES / 8, 256>>>(xin, batch, out);
    pool_div_kernel<<<(N_GRAPHS * DIM + 255) / 256, 256>>>(out);
}

// round 14
// speedup vs baseline: 1.8531x; 1.1190x over previous
#include <cuda_runtime.h>
#include <cuda_fp16.h>
#include <cstdint>

#define N_NODES  4096
#define N_EDGES  16384
#define N_GRAPHS 128
#define DIM      64     // IN = H = 64 for all layers
#define EDIM     16
#define HD       4096   // DIM*DIM, edge-MLP width

// ---------------------------------------------------------------------------
// Scratch (static __device__ globals: no allocation anywhere)
// ---------------------------------------------------------------------------
__device__ __half g_h[N_EDGES * HD];      // 134 MB: relu(ea@w1+b1) in fp16
__device__ __half g_w2h[HD * HD];         // 32 MB: w2 transposed [N,K] in fp16
__device__ float  g_feat[2][N_NODES * DIM];
__device__ float  g_agg[N_NODES * DIM];
__device__ float  g_cnt[N_NODES];
__device__ float  g_gcnt[N_GRAPHS];

// ---------------------------------------------------------------------------
// Utility kernels
// ---------------------------------------------------------------------------
__global__ void zero_kernel(float* __restrict__ p, int n) {
    int i = blockIdx.x * blockDim.x + threadIdx.x;
    if (i < n) p[i] = 0.0f;
}

__global__ void cnt_kernel(const int* __restrict__ ei) {
    int e = blockIdx.x * blockDim.x + threadIdx.x;
    if (e < N_EDGES) atomicAdd(&g_cnt[ei[N_EDGES + e]], 1.0f);
}

// w2 [K,N] fp32 -> g_w2h [N,K] fp16 (B operand, K-contiguous)
__global__ void round_w2T_kernel(const float* __restrict__ w2) {
    __shared__ float tile[32][33];
    int k0 = blockIdx.y * 32, nn0 = blockIdx.x * 32;
    int tx = threadIdx.x, ty = threadIdx.y;  // (32,8)
#pragma unroll
    for (int r = 0; r < 4; r++)
        tile[ty + 8 * r][tx] = w2[(size_t)(k0 + ty + 8 * r) * HD + nn0 + tx];
    __syncthreads();
#pragma unroll
    for (int r = 0; r < 4; r++)
        g_w2h[(size_t)(nn0 + ty + 8 * r) * HD + k0 + tx] =
            __float2half_rn(tile[tx][ty + 8 * r]);
}

// ---------------------------------------------------------------------------
// h = relu(edge_attr @ w1 + b1), stored fp16 (A operand).
// ---------------------------------------------------------------------------
__global__ void edge_mlp_kernel(const float* __restrict__ ea,
                                const float* __restrict__ w1,
                                const float* __restrict__ b1) {
    __shared__ float sa[32][20];
    __shared__ float sw[16][128];
    const int e0 = blockIdx.x * 32;
    const int c0 = blockIdx.y * 128;
    const int t  = threadIdx.x;

    if (t < 128) {
        int e = t >> 2, d4 = (t & 3) << 2;
        float4 v = *reinterpret_cast<const float4*>(ea + (e0 + e) * EDIM + d4);
        *reinterpret_cast<float4*>(&sa[e][d4]) = v;
    }
#pragma unroll
    for (int i = 0; i < 2; i++) {
        int id = t + i * 256;
        int d = id >> 5, c4 = (id & 31) << 2;
        float4 v = *reinterpret_cast<const float4*>(w1 + d * HD + c0 + c4);
        *reinterpret_cast<float4*>(&sw[d][c4]) = v;
    }
    __syncthreads();

    const int lc = t & 127;
    const int eh = t >> 7;
    float wreg[16];
#pragma unroll
    for (int d = 0; d < 16; d++) wreg[d] = sw[d][lc];
    const float bias = __ldg(b1 + c0 + lc);

#pragma unroll
    for (int j = 0; j < 16; j++) {
        int e = eh + j * 2;
        float acc = bias;
#pragma unroll
        for (int d = 0; d < 16; d++) acc += sa[e][d] * wreg[d];
        acc = fmaxf(acc, 0.0f);
        g_h[(size_t)(e0 + e) * HD + c0 + lc] = __float2half_rn(acc);
    }
}

// ---------------------------------------------------------------------------
// Fused: theta = g_h @ g_w2h^T + b2 and message scatter into g_agg.
// [M=16384, N=4096, K=4096], FP16 mma m16n8k16, ldmatrix fragments.
// BM=128 BN=128 BK=32, 3-stage cp.async (wait_group 1), 256 thr, 2 CTAs/SM.
// Warp grid 2x4, warp tile 64x32. Rows = edges; each warp's 32-col slab maps
// to ONE input channel i_w=(n0>>6)+(wn>>1): epilogue does
// atomicAdd(g_agg[dst*64 + (col&63)], x[src,i_w]*(acc+b2[col])) — theta is
// never materialized. Smem rows stride 80 B: each ldmatrix 8-row phase hits
// banks {20i mod 32} = all-distinct. acc=64 regs/thread.
// ---------------------------------------------------------------------------
#define BM 128
#define BN 128
#define BK 32
#define ROWB 80                              // bytes per smem row (40 halfs)
#define A_STAGE_B (BM * ROWB)                // 10240 B
#define B_STAGE_B (BN * ROWB)                // 10240 B
#define STAGE_B   (A_STAGE_B + B_STAGE_B)    // 20480 B
#define NSTAGE 3
#define SMEM_BYTES (NSTAGE * STAGE_B)        // 61440 B

__global__ __launch_bounds__(256, 2)
void gemm_fused_kernel(const float* __restrict__ b2,
                       const float* __restrict__ xin,
                       const int* __restrict__ ei) {
    extern __shared__ char smem[];
    const int t  = threadIdx.x;
    const int m0 = blockIdx.y * BM;
    const int n0 = blockIdx.x * BN;
    const int warp = t >> 5, lane = t & 31;
    const int wm = warp >> 2, wn = warp & 3;      // 2x4 warp grid
    const int g = lane >> 2, q = lane & 3;

    const uint32_t sbase = (uint32_t)__cvta_generic_to_shared(smem);

    // ldmatrix per-lane base offsets (bytes within a stage)
    // A x4: M0 rows 0-7 k0-7 | M1 rows 8-15 k0-7 | M2 rows 0-7 k8-15 | M3 rows 8-15 k8-15
    const uint32_t a_lane = (uint32_t)((wm * 64 + (lane & 15)) * ROWB + ((lane >> 4) << 4));
    // B x4 (pair p): M0 n-rows 0-7 k0-7 | M1 rows 0-7 k8-15 | M2 rows 8-15 k0-7 | M3 rows 8-15 k8-15
    const uint32_t b_lane = (uint32_t)(A_STAGE_B +
        (wn * 32 + ((lane >> 4) << 3) + (lane & 7)) * ROWB + (((lane >> 3) & 1) << 4));

    auto load_tile = [&](int kt) {
        uint32_t base = sbase + (uint32_t)((kt % NSTAGE) * STAGE_B);
#pragma unroll
        for (int i = 0; i < 2; i++) {              // A: 128 rows x 4 x 16B
            int c = t + i * 256;
            int row = c >> 2, ch = c & 3;
            const char* src = (const char*)(g_h + (size_t)(m0 + row) * HD + kt * BK) + ch * 16;
            asm volatile("cp.async.cg.shared.global [%0], [%1], 16;\n"
                :: "r"(base + (uint32_t)(row * ROWB + ch * 16)), "l"(src));
        }
#pragma unroll
        for (int i = 0; i < 2; i++) {              // B: 128 rows x 4 x 16B
            int c = t + i * 256;
            int row = c >> 2, ch = c & 3;
            const char* src = (const char*)(g_w2h + (size_t)(n0 + row) * HD + kt * BK) + ch * 16;
            asm volatile("cp.async.cg.shared.global [%0], [%1], 16;\n"
                :: "r"(base + (uint32_t)(A_STAGE_B + row * ROWB + ch * 16)), "l"(src));
        }
        asm volatile("cp.async.commit_group;\n" ::: "memory");
    };

    float acc[4][4][4];
#pragma unroll
    for (int mt = 0; mt < 4; mt++)
#pragma unroll
        for (int nt = 0; nt < 4; nt++)
#pragma unroll
            for (int r = 0; r < 4; r++) acc[mt][nt][r] = 0.0f;

    const int KT = HD / BK;   // 128
    load_tile(0); load_tile(1);

    for (int kt = 0; kt < KT; kt++) {
        if (kt + 1 < KT)
            asm volatile("cp.async.wait_group 1;\n" ::: "memory");
        else
            asm volatile("cp.async.wait_group 0;\n" ::: "memory");
        __syncthreads();
        if (kt + 2 < KT) load_tile(kt + 2);

        const uint32_t stg = sbase + (uint32_t)((kt % NSTAGE) * STAGE_B);

#pragma unroll
        for (int ks = 0; ks < 2; ks++) {          // two k16 steps per BK=32
            const uint32_t koff = (uint32_t)(ks * 32);   // 16 halfs = 32 B
            uint32_t af[4][4];
#pragma unroll
            for (int mt = 0; mt < 4; mt++) {
                asm volatile(
                    "ldmatrix.sync.aligned.m8n8.x4.shared.b16 {%0,%1,%2,%3}, [%4];\n"
                    : "=r"(af[mt][0]), "=r"(af[mt][1]),
                      "=r"(af[mt][2]), "=r"(af[mt][3])
                    : "r"(stg + a_lane + (uint32_t)(mt * 16 * ROWB) + koff));
            }
            uint32_t bf[4][2];
#pragma unroll
            for (int p = 0; p < 2; p++) {
                asm volatile(
                    "ldmatrix.sync.aligned.m8n8.x4.shared.b16 {%0,%1,%2,%3}, [%4];\n"
                    : "=r"(bf[2 * p][0]), "=r"(bf[2 * p][1]),
                      "=r"(bf[2 * p + 1][0]), "=r"(bf[2 * p + 1][1])
                    : "r"(stg + b_lane + (uint32_t)(p * 16 * ROWB) + koff));
            }
#pragma unroll
            for (int mt = 0; mt < 4; mt++)
#pragma unroll
                for (int nt = 0; nt < 4; nt++) {
                    asm volatile(
                        "mma.sync.aligned.m16n8k16.row.col.f32.f16.f16.f32 "
                        "{%0,%1,%2,%3}, {%4,%5,%6,%7}, {%8,%9}, {%0,%1,%2,%3};\n"
                        : "+f"(acc[mt][nt][0]), "+f"(acc[mt][nt][1]),
                          "+f"(acc[mt][nt][2]), "+f"(acc[mt][nt][3])
                        : "r"(af[mt][0]), "r"(af[mt][1]),
                          "r"(af[mt][2]), "r"(af[mt][3]),
                          "r"(bf[nt][0]), "r"(bf[nt][1]));
                }
        }
    }

    // Fused epilogue: msg contribution for this warp's single input channel,
    // scattered straight into g_agg[dst]. theta = acc + b2.
    const int i_w = (n0 >> 6) + (wn >> 1);
#pragma unroll
    for (int mt = 0; mt < 4; mt++) {
#pragma unroll
        for (int hh = 0; hh < 2; hh++) {
            int e = m0 + wm * 64 + mt * 16 + g + hh * 8;
            int src = __ldg(ei + e);
            int dst = __ldg(ei + N_EDGES + e);
            float xv = __ldg(xin + src * DIM + i_w);
            float* aggp = g_agg + dst * DIM;
#pragma unroll
            for (int nt = 0; nt < 4; nt++) {
                int col = n0 + wn * 32 + nt * 8 + 2 * q;
                int o = col & 63;
                float t0 = acc[mt][nt][2 * hh]     + __ldg(b2 + col);
                float t1 = acc[mt][nt][2 * hh + 1] + __ldg(b2 + col + 1);
                atomicAdd(aggp + o,     xv * t0);
                atomicAdd(aggp + o + 1, xv * t1);
            }
        }
    }
}

// ---------------------------------------------------------------------------
// out[v] = relu(agg[v]/max(cnt,1) + x[v] @ root + bias); one warp per node
// ---------------------------------------------------------------------------
__global__ void node_update_kernel(const float* __restrict__ x,
                                   const float* __restrict__ root,
                                   const float* __restrict__ bias,
                                   float* __restrict__ out) {
    int v = (blockIdx.x * blockDim.x + threadIdx.x) >> 5;
    int lane = threadIdx.x & 31;
    if (v >= N_NODES) return;
    float inv = 1.0f / fmaxf(g_cnt[v], 1.0f);
    float a0 = g_agg[v * DIM + lane] * inv + __ldg(bias + lane);
    float a1 = g_agg[v * DIM + 32 + lane] * inv + __ldg(bias + 32 + lane);
    float xv0 = x[v * DIM + lane];
    float xv1 = x[v * DIM + 32 + lane];
#pragma unroll 8
    for (int i = 0; i < 32; i++) {
        float xi = __shfl_sync(0xffffffffu, xv0, i);
        a0 += xi * __ldg(root + i * 64 + lane);
        a1 += xi * __ldg(root + i * 64 + 32 + lane);
    }
#pragma unroll 8
    for (int i = 0; i < 32; i++) {
        float xi = __shfl_sync(0xffffffffu, xv1, i);
        a0 += xi * __ldg(root + (32 + i) * 64 + lane);
        a1 += xi * __ldg(root + (32 + i) * 64 + 32 + lane);
    }
    out[v * DIM + lane] = fmaxf(a0, 0.0f);
    out[v * DIM + 32 + lane] = fmaxf(a1, 0.0f);
}

// ---------------------------------------------------------------------------
// Global mean pool
// ---------------------------------------------------------------------------
__global__ void pool_sum_kernel(const float* __restrict__ y,
                                const int* __restrict__ batch,
                                float* __restrict__ out) {
    int v = (blockIdx.x * blockDim.x + threadIdx.x) >> 5;
    int lane = threadIdx.x & 31;
    if (v >= N_NODES) return;
    int gr = batch[v];
    atomicAdd(&out[gr * DIM + lane], y[v * DIM + lane]);
    atomicAdd(&out[gr * DIM + 32 + lane], y[v * DIM + 32 + lane]);
    if (lane == 0) atomicAdd(&g_gcnt[gr], 1.0f);
}

__global__ void pool_div_kernel(float* __restrict__ out) {
    int i = blockIdx.x * blockDim.x + threadIdx.x;
    if (i < N_GRAPHS * DIM) out[i] /= fmaxf(g_gcnt[i / DIM], 1.0f);
}

// ---------------------------------------------------------------------------
// Launch
// ---------------------------------------------------------------------------
extern "C" void kernel_launch(void* const* d_in, const int* in_sizes, int n_in,
                              void* d_out, int out_size) {
    (void)in_sizes; (void)n_in; (void)out_size;
    const float* x     = (const float*)d_in[0];
    const int*   ei    = (const int*)d_in[1];
    const float* ea    = (const float*)d_in[2];
    const int*   batch = (const int*)d_in[3];
    const float* W[3][6];
    for (int l = 0; l < 3; l++)
        for (int j = 0; j < 6; j++)
            W[l][j] = (const float*)d_in[4 + l * 6 + j];   // w1,b1,w2,b2,root,bias
    float* out = (float*)d_out;

    cudaFuncSetAttribute(gemm_fused_kernel,
                         cudaFuncAttributeMaxDynamicSharedMemorySize, SMEM_BYTES);

    float *p_cnt, *p_agg, *p_feat, *p_gcnt;
    cudaGetSymbolAddress((void**)&p_cnt,  g_cnt);
    cudaGetSymbolAddress((void**)&p_agg,  g_agg);
    cudaGetSymbolAddress((void**)&p_feat, g_feat);
    cudaGetSymbolAddress((void**)&p_gcnt, g_gcnt);

    zero_kernel<<<(N_NODES + 255) / 256, 256>>>(p_cnt, N_NODES);
    cnt_kernel<<<(N_EDGES + 255) / 256, 256>>>(ei);

    const float* xin = x;
    for (int l = 0; l < 3; l++) {
        float* xout = p_feat + (l & 1) * (N_NODES * DIM);

        dim3 gmlp(N_EDGES / 32, HD / 128);
        edge_mlp_kernel<<<gmlp, 256>>>(ea, W[l][0], W[l][1]);

        round_w2T_kernel<<<dim3(HD / 32, HD / 32), dim3(32, 8)>>>(W[l][2]);

        zero_kernel<<<(N_NODES * DIM + 255) / 256, 256>>>(p_agg, N_NODES * DIM);

        dim3 gg(HD / BN, N_EDGES / BM);   // (32, 128)
        gemm_fused_kernel<<<gg, 256, SMEM_BYTES>>>(W[l][3], xin, ei);

        node_update_kernel<<<N_NODES / 8, 256>>>(xin, W[l][4], W[l][5], xout);
        xin = xout;
    }

    zero_kernel<<<(N_GRAPHS * DIM + 255) / 256, 256>>>(out, N_GRAPHS * DIM);
    zero_kernel<<<1, 256>>>(p_gcnt, N_GRAPHS);
    pool_sum_kernel<<<N_NODES / 8, 256>>>(xin, batch, out);
    pool_div_kernel<<<(N_GRAPHS * DIM + 255) / 256, 256>>>(out);
}

// round 15
// speedup vs baseline: 2.1288x; 1.1488x over previous
#include <cuda_runtime.h>
#include <cuda_fp16.h>
#include <cstdint>

#define N_NODES  4096
#define N_EDGES  16384
#define N_GRAPHS 128
#define DIM      64     // IN = H = 64 for all layers
#define EDIM     16
#define HD       4096   // DIM*DIM, edge-MLP width

// ---------------------------------------------------------------------------
// Scratch (static __device__ globals: no allocation anywhere)
// ---------------------------------------------------------------------------
__device__ __half g_h[N_EDGES * HD];      // 134 MB: relu(ea@w1+b1) in fp16
__device__ __half g_w2h[HD * HD];         // 32 MB: w2 transposed [N,K] in fp16
__device__ float  g_feat[2][N_NODES * DIM];
__device__ float  g_agg[N_NODES * DIM];
__device__ float  g_cnt[N_NODES];
__device__ float  g_gcnt[N_GRAPHS];

// ---------------------------------------------------------------------------
// Utility kernels
// ---------------------------------------------------------------------------
__global__ void zero_kernel(float* __restrict__ p, int n) {
    int i = blockIdx.x * blockDim.x + threadIdx.x;
    if (i < n) p[i] = 0.0f;
}

__global__ void cnt_kernel(const int* __restrict__ ei) {
    int e = blockIdx.x * blockDim.x + threadIdx.x;
    if (e < N_EDGES) atomicAdd(&g_cnt[ei[N_EDGES + e]], 1.0f);
}

// w2 [K,N] fp32 -> g_w2h [N,K] fp16 (B operand, K-contiguous)
__global__ void round_w2T_kernel(const float* __restrict__ w2) {
    __shared__ float tile[32][33];
    int k0 = blockIdx.y * 32, nn0 = blockIdx.x * 32;
    int tx = threadIdx.x, ty = threadIdx.y;  // (32,8)
#pragma unroll
    for (int r = 0; r < 4; r++)
        tile[ty + 8 * r][tx] = w2[(size_t)(k0 + ty + 8 * r) * HD + nn0 + tx];
    __syncthreads();
#pragma unroll
    for (int r = 0; r < 4; r++)
        g_w2h[(size_t)(nn0 + ty + 8 * r) * HD + k0 + tx] =
            __float2half_rn(tile[tx][ty + 8 * r]);
}

// ---------------------------------------------------------------------------
// h = relu(edge_attr @ w1 + b1), stored fp16 (A operand).
// ---------------------------------------------------------------------------
__global__ void edge_mlp_kernel(const float* __restrict__ ea,
                                const float* __restrict__ w1,
                                const float* __restrict__ b1) {
    __shared__ float sa[32][20];
    __shared__ float sw[16][128];
    const int e0 = blockIdx.x * 32;
    const int c0 = blockIdx.y * 128;
    const int t  = threadIdx.x;

    if (t < 128) {
        int e = t >> 2, d4 = (t & 3) << 2;
        float4 v = *reinterpret_cast<const float4*>(ea + (e0 + e) * EDIM + d4);
        *reinterpret_cast<float4*>(&sa[e][d4]) = v;
    }
#pragma unroll
    for (int i = 0; i < 2; i++) {
        int id = t + i * 256;
        int d = id >> 5, c4 = (id & 31) << 2;
        float4 v = *reinterpret_cast<const float4*>(w1 + d * HD + c0 + c4);
        *reinterpret_cast<float4*>(&sw[d][c4]) = v;
    }
    __syncthreads();

    const int lc = t & 127;
    const int eh = t >> 7;
    float wreg[16];
#pragma unroll
    for (int d = 0; d < 16; d++) wreg[d] = sw[d][lc];
    const float bias = __ldg(b1 + c0 + lc);

#pragma unroll
    for (int j = 0; j < 16; j++) {
        int e = eh + j * 2;
        float acc = bias;
#pragma unroll
        for (int d = 0; d < 16; d++) acc += sa[e][d] * wreg[d];
        acc = fmaxf(acc, 0.0f);
        g_h[(size_t)(e0 + e) * HD + c0 + lc] = __float2half_rn(acc);
    }
}

// ---------------------------------------------------------------------------
// Fused: theta = g_h @ g_w2h^T + b2 and message scatter into g_agg.
// [M=16384, N=4096, K=4096], FP16 mma m16n8k16, ldmatrix fragments.
// BM=128 BN=128 BK=64, 2-stage cp.async, 256 thr, 2 CTAs/SM.
// Row stride 144 B (16B-aligned for cp.async; ldmatrix phase banks
// 36i mod 32 = {0,4,...,28} all-distinct). 64 iters x 4 k16-steps.
// Each warp's 32-col slab maps to ONE input channel i_w=(n0>>6)+(wn>>1):
// epilogue atomicAdds x[src,i_w]*(acc+b2) into g_agg[dst] — theta never
// materialized. acc=64 regs/thread.
// ---------------------------------------------------------------------------
#define BM 128
#define BN 128
#define BK 64
#define ROWB 144                             // bytes per smem row (64 halfs + pad)
#define A_STAGE_B (BM * ROWB)                // 18432 B
#define B_STAGE_B (BN * ROWB)                // 18432 B
#define STAGE_B   (A_STAGE_B + B_STAGE_B)    // 36864 B
#define NSTAGE 2
#define SMEM_BYTES (NSTAGE * STAGE_B)        // 73728 B

__global__ __launch_bounds__(256, 2)
void gemm_fused_kernel(const float* __restrict__ b2,
                       const float* __restrict__ xin,
                       const int* __restrict__ ei) {
    extern __shared__ char smem[];
    const int t  = threadIdx.x;
    const int m0 = blockIdx.y * BM;
    const int n0 = blockIdx.x * BN;
    const int warp = t >> 5, lane = t & 31;
    const int wm = warp >> 2, wn = warp & 3;      // 2x4 warp grid
    const int g = lane >> 2, q = lane & 3;

    const uint32_t sbase = (uint32_t)__cvta_generic_to_shared(smem);

    // ldmatrix per-lane base offsets (bytes within a stage)
    // A x4: M0 rows 0-7 k0-7 | M1 rows 8-15 k0-7 | M2 rows 0-7 k8-15 | M3 rows 8-15 k8-15
    const uint32_t a_lane = (uint32_t)((wm * 64 + (lane & 15)) * ROWB + ((lane >> 4) << 4));
    // B x4: n-rows 0-7 k0-7 | rows 0-7 k8-15 | rows 8-15 k0-7 | rows 8-15 k8-15
    const uint32_t b_lane = (uint32_t)(A_STAGE_B +
        (wn * 32 + ((lane >> 4) << 3) + (lane & 7)) * ROWB + (((lane >> 3) & 1) << 4));

    auto load_tile = [&](int kt) {
        uint32_t base = sbase + (uint32_t)((kt & 1) * STAGE_B);
#pragma unroll
        for (int i = 0; i < 4; i++) {              // A: 128 rows x 8 x 16B
            int c = t + i * 256;
            int row = c >> 3, ch = c & 7;
            const char* src = (const char*)(g_h + (size_t)(m0 + row) * HD + kt * BK) + ch * 16;
            asm volatile("cp.async.cg.shared.global [%0], [%1], 16;\n"
                :: "r"(base + (uint32_t)(row * ROWB + ch * 16)), "l"(src));
        }
#pragma unroll
        for (int i = 0; i < 4; i++) {              // B: 128 rows x 8 x 16B
            int c = t + i * 256;
            int row = c >> 3, ch = c & 7;
            const char* src = (const char*)(g_w2h + (size_t)(n0 + row) * HD + kt * BK) + ch * 16;
            asm volatile("cp.async.cg.shared.global [%0], [%1], 16;\n"
                :: "r"(base + (uint32_t)(A_STAGE_B + row * ROWB + ch * 16)), "l"(src));
        }
        asm volatile("cp.async.commit_group;\n" ::: "memory");
    };

    float acc[4][4][4];
#pragma unroll
    for (int mt = 0; mt < 4; mt++)
#pragma unroll
        for (int nt = 0; nt < 4; nt++)
#pragma unroll
            for (int r = 0; r < 4; r++) acc[mt][nt][r] = 0.0f;

    const int KT = HD / BK;   // 64
    load_tile(0);

    for (int kt = 0; kt < KT; kt++) {
        asm volatile("cp.async.wait_group 0;\n" ::: "memory");
        __syncthreads();
        if (kt + 1 < KT) load_tile(kt + 1);

        const uint32_t stg = sbase + (uint32_t)((kt & 1) * STAGE_B);

#pragma unroll
        for (int ks = 0; ks < 4; ks++) {          // four k16 steps per BK=64
            const uint32_t koff = (uint32_t)(ks * 32);   // 16 halfs = 32 B
            uint32_t af[4][4];
#pragma unroll
            for (int mt = 0; mt < 4; mt++) {
                asm volatile(
                    "ldmatrix.sync.aligned.m8n8.x4.shared.b16 {%0,%1,%2,%3}, [%4];\n"
                    : "=r"(af[mt][0]), "=r"(af[mt][1]),
                      "=r"(af[mt][2]), "=r"(af[mt][3])
                    : "r"(stg + a_lane + (uint32_t)(mt * 16 * ROWB) + koff));
            }
            uint32_t bf[4][2];
#pragma unroll
            for (int p = 0; p < 2; p++) {
                asm volatile(
                    "ldmatrix.sync.aligned.m8n8.x4.shared.b16 {%0,%1,%2,%3}, [%4];\n"
                    : "=r"(bf[2 * p][0]), "=r"(bf[2 * p][1]),
                      "=r"(bf[2 * p + 1][0]), "=r"(bf[2 * p + 1][1])
                    : "r"(stg + b_lane + (uint32_t)(p * 16 * ROWB) + koff));
            }
#pragma unroll
            for (int mt = 0; mt < 4; mt++)
#pragma unroll
                for (int nt = 0; nt < 4; nt++) {
                    asm volatile(
                        "mma.sync.aligned.m16n8k16.row.col.f32.f16.f16.f32 "
                        "{%0,%1,%2,%3}, {%4,%5,%6,%7}, {%8,%9}, {%0,%1,%2,%3};\n"
                        : "+f"(acc[mt][nt][0]), "+f"(acc[mt][nt][1]),
                          "+f"(acc[mt][nt][2]), "+f"(acc[mt][nt][3])
                        : "r"(af[mt][0]), "r"(af[mt][1]),
                          "r"(af[mt][2]), "r"(af[mt][3]),
                          "r"(bf[nt][0]), "r"(bf[nt][1]));
                }
        }
    }

    // Fused epilogue: msg contribution for this warp's single input channel,
    // scattered straight into g_agg[dst]. theta = acc + b2.
    const int i_w = (n0 >> 6) + (wn >> 1);
#pragma unroll
    for (int mt = 0; mt < 4; mt++) {
#pragma unroll
        for (int hh = 0; hh < 2; hh++) {
            int e = m0 + wm * 64 + mt * 16 + g + hh * 8;
            int src = __ldg(ei + e);
            int dst = __ldg(ei + N_EDGES + e);
            float xv = __ldg(xin + src * DIM + i_w);
            float* aggp = g_agg + dst * DIM;
#pragma unroll
            for (int nt = 0; nt < 4; nt++) {
                int col = n0 + wn * 32 + nt * 8 + 2 * q;
                int o = col & 63;
                float t0 = acc[mt][nt][2 * hh]     + __ldg(b2 + col);
                float t1 = acc[mt][nt][2 * hh + 1] + __ldg(b2 + col + 1);
                atomicAdd(aggp + o,     xv * t0);
                atomicAdd(aggp + o + 1, xv * t1);
            }
        }
    }
}

// ---------------------------------------------------------------------------
// out[v] = relu(agg[v]/max(cnt,1) + x[v] @ root + bias); one warp per node
// ---------------------------------------------------------------------------
__global__ void node_update_kernel(const float* __restrict__ x,
                                   const float* __restrict__ root,
                                   const float* __restrict__ bias,
                                   float* __restrict__ out) {
    int v = (blockIdx.x * blockDim.x + threadIdx.x) >> 5;
    int lane = threadIdx.x & 31;
    if (v >= N_NODES) return;
    float inv = 1.0f / fmaxf(g_cnt[v], 1.0f);
    float a0 = g_agg[v * DIM + lane] * inv + __ldg(bias + lane);
    float a1 = g_agg[v * DIM + 32 + lane] * inv + __ldg(bias + 32 + lane);
    float xv0 = x[v * DIM + lane];
    float xv1 = x[v * DIM + 32 + lane];
#pragma unroll 8
    for (int i = 0; i < 32; i++) {
        float xi = __shfl_sync(0xffffffffu, xv0, i);
        a0 += xi * __ldg(root + i * 64 + lane);
        a1 += xi * __ldg(root + i * 64 + 32 + lane);
    }
#pragma unroll 8
    for (int i = 0; i < 32; i++) {
        float xi = __shfl_sync(0xffffffffu, xv1, i);
        a0 += xi * __ldg(root + (32 + i) * 64 + lane);
        a1 += xi * __ldg(root + (32 + i) * 64 + 32 + lane);
    }
    out[v * DIM + lane] = fmaxf(a0, 0.0f);
    out[v * DIM + 32 + lane] = fmaxf(a1, 0.0f);
}

// ---------------------------------------------------------------------------
// Global mean pool
// ---------------------------------------------------------------------------
__global__ void pool_sum_kernel(const float* __restrict__ y,
                                const int* __restrict__ batch,
                                float* __restrict__ out) {
    int v = (blockIdx.x * blockDim.x + threadIdx.x) >> 5;
    int lane = threadIdx.x & 31;
    if (v >= N_NODES) return;
    int gr = batch[v];
    atomicAdd(&out[gr * DIM + lane], y[v * DIM + lane]);
    atomicAdd(&out[gr * DIM + 32 + lane], y[v * DIM + 32 + lane]);
    if (lane == 0) atomicAdd(&g_gcnt[gr], 1.0f);
}

__global__ void pool_div_kernel(float* __restrict__ out) {
    int i = blockIdx.x * blockDim.x + threadIdx.x;
    if (i < N_GRAPHS * DIM) out[i] /= fmaxf(g_gcnt[i / DIM], 1.0f);
}

// ---------------------------------------------------------------------------
// Launch
// ---------------------------------------------------------------------------
extern "C" void kernel_launch(void* const* d_in, const int* in_sizes, int n_in,
                              void* d_out, int out_size) {
    (void)in_sizes; (void)n_in; (void)out_size;
    const float* x     = (const float*)d_in[0];
    const int*   ei    = (const int*)d_in[1];
    const float* ea    = (const float*)d_in[2];
    const int*   batch = (const int*)d_in[3];
    const float* W[3][6];
    for (int l = 0; l < 3; l++)
        for (int j = 0; j < 6; j++)
            W[l][j] = (const float*)d_in[4 + l * 6 + j];   // w1,b1,w2,b2,root,bias
    float* out = (float*)d_out;

    cudaFuncSetAttribute(gemm_fused_kernel,
                         cudaFuncAttributeMaxDynamicSharedMemorySize, SMEM_BYTES);

    float *p_cnt, *p_agg, *p_feat, *p_gcnt;
    cudaGetSymbolAddress((void**)&p_cnt,  g_cnt);
    cudaGetSymbolAddress((void**)&p_agg,  g_agg);
    cudaGetSymbolAddress((void**)&p_feat, g_feat);
    cudaGetSymbolAddress((void**)&p_gcnt, g_gcnt);

    zero_kernel<<<(N_NODES + 255) / 256, 256>>>(p_cnt, N_NODES);
    cnt_kernel<<<(N_EDGES + 255) / 256, 256>>>(ei);

    const float* xin = x;
    for (int l = 0; l < 3; l++) {
        float* xout = p_feat + (l & 1) * (N_NODES * DIM);

        dim3 gmlp(N_EDGES / 32, HD / 128);
        edge_mlp_kernel<<<gmlp, 256>>>(ea, W[l][0], W[l][1]);

        round_w2T_kernel<<<dim3(HD / 32, HD / 32), dim3(32, 8)>>>(W[l][2]);

        zero_kernel<<<(N_NODES * DIM + 255) / 256, 256>>>(p_agg, N_NODES * DIM);

        dim3 gg(HD / BN, N_EDGES / BM);   // (32, 128)
        gemm_fused_kernel<<<gg, 256, SMEM_BYTES>>>(W[l][3], xin, ei);

        node_update_kernel<<<N_NODES / 8, 256>>>(xin, W[l][4], W[l][5], xout);
        xin = xout;
    }

    zero_kernel<<<(N_GRAPHS * DIM + 255) / 256, 256>>>(out, N_GRAPHS * DIM);
    zero_kernel<<<1, 256>>>(p_gcnt, N_GRAPHS);
    pool_sum_kernel<<<N_NODES / 8, 256>>>(xin, batch, out);
    pool_div_kernel<<<(N_GRAPHS * DIM + 255) / 256, 256>>>(out);
}